// round 9
// baseline (speedup 1.0000x reference)
#include <cuda_runtime.h>

// EfConv: out[n, k*64+o] = b[o] + sum_{e: dst[e]==n} edge_feat[e,k] * z[src[e], o]
// where z = node_feat @ W^T.
//
// Pipeline:
//   0. zhist_kernel : z = nf @ W^T (64 nodes/block, 4x4 reg tile) + histogram
//   1. scan_kernel  : smem-resident scan (warp-shuffle hierarchy); re-zeros counts
//   2. build_kernel : scatter (src<<8) + ef rows into CSR order (16 edges/thr)
//   3. gather_kernel: TWO warps per node (column-split), 1 col/lane, 8 packed
//                     f32x2 accumulators -> low regs, high occupancy; batch
//                     resolve into smem; z loads pipelined across 4-edge groups.

#define MAX_N 50000
#define MAX_E 800000

__device__ float g_z[MAX_N * 64];
__device__ int   g_counts[MAX_N];
__device__ int   g_offsets[MAX_N + 1];
__device__ int   g_cursor[MAX_N];
__device__ int   g_srcs[MAX_E];          // src<<8 (byte offset of z row)
__device__ float g_efs[(size_t)MAX_E * 8];

// ---------------------------------------------------------------------------
__global__ __launch_bounds__(256)
void zhist_kernel(const float* __restrict__ nf,
                  const float* __restrict__ W,
                  const int* __restrict__ dst, int N, int E) {
    __shared__ float Ws[64 * 68];
    __shared__ float nfs[64 * 64];
    int tid = threadIdx.x;

#pragma unroll
    for (int it = 0; it < 16; ++it) {
        int idx = it * 256 + tid;            // idx = o*64 + i
        int o = idx >> 6, i = idx & 63;
        Ws[i * 68 + o] = W[idx];
    }

    int nb = blockIdx.x * 64;
#pragma unroll
    for (int it = 0; it < 16; ++it) {
        int idx = it * 256 + tid;
        int n = nb + (idx >> 6);
        nfs[idx] = (n < N) ? nf[(size_t)n * 64 + (idx & 63)] : 0.0f;
    }

    int gs = gridDim.x * 256;
    int quads = (E + 3) >> 2;
    for (int u = blockIdx.x * 256 + tid; u < quads; u += gs) {
        int e4 = u * 4;
        if (e4 + 3 < E) {
            int4 d = *(const int4*)(dst + e4);
            atomicAdd(&g_counts[d.x], 1);
            atomicAdd(&g_counts[d.y], 1);
            atomicAdd(&g_counts[d.z], 1);
            atomicAdd(&g_counts[d.w], 1);
        } else {
            for (int e = e4; e < E; ++e) atomicAdd(&g_counts[dst[e]], 1);
        }
    }
    __syncthreads();

    int ng = tid >> 4;
    int ow = tid & 15;
    float acc[4][4];
#pragma unroll
    for (int j = 0; j < 4; ++j)
#pragma unroll
        for (int q = 0; q < 4; ++q) acc[j][q] = 0.0f;

#pragma unroll 4
    for (int i = 0; i < 64; ++i) {
        float4 wv = *(const float4*)(Ws + i * 68 + ow * 4);
        float a0 = nfs[(ng * 4 + 0) * 64 + i];
        float a1 = nfs[(ng * 4 + 1) * 64 + i];
        float a2 = nfs[(ng * 4 + 2) * 64 + i];
        float a3 = nfs[(ng * 4 + 3) * 64 + i];
        acc[0][0] += a0 * wv.x; acc[0][1] += a0 * wv.y; acc[0][2] += a0 * wv.z; acc[0][3] += a0 * wv.w;
        acc[1][0] += a1 * wv.x; acc[1][1] += a1 * wv.y; acc[1][2] += a1 * wv.z; acc[1][3] += a1 * wv.w;
        acc[2][0] += a2 * wv.x; acc[2][1] += a2 * wv.y; acc[2][2] += a2 * wv.z; acc[2][3] += a2 * wv.w;
        acc[3][0] += a3 * wv.x; acc[3][1] += a3 * wv.y; acc[3][2] += a3 * wv.z; acc[3][3] += a3 * wv.w;
    }

#pragma unroll
    for (int j = 0; j < 4; ++j) {
        int n = nb + ng * 4 + j;
        if (n < N)
            *(float4*)(g_z + (size_t)n * 64 + ow * 4) =
                make_float4(acc[j][0], acc[j][1], acc[j][2], acc[j][3]);
    }
}

// ---------------------------------------------------------------------------
__global__ __launch_bounds__(1024)
void scan_kernel(int N) {
    extern __shared__ int ss[];
    int* s     = ss;          // [N]
    int* wsum  = ss + N;      // [32]
    int t    = threadIdx.x;
    int lane = t & 31;
    int wid  = t >> 5;
    int C = (N + 1023) >> 10;

    for (int i = t; i < N; i += 1024) {
        s[i] = g_counts[i];
        g_counts[i] = 0;
    }
    __syncthreads();

    int base = t * C;
    int sum = 0;
    for (int i = 0; i < C; ++i) {
        int n = base + i;
        if (n < N) sum += s[n];
    }

    int v = sum;
#pragma unroll
    for (int d = 1; d < 32; d <<= 1) {
        int u = __shfl_up_sync(0xffffffffu, v, d);
        if (lane >= d) v += u;
    }
    if (lane == 31) wsum[wid] = v;
    __syncthreads();

    if (wid == 0) {
        int wv = wsum[lane];
#pragma unroll
        for (int d = 1; d < 32; d <<= 1) {
            int u = __shfl_up_sync(0xffffffffu, wv, d);
            if (lane >= d) wv += u;
        }
        wsum[lane] = wv;
    }
    __syncthreads();

    int excl = v - sum + (wid > 0 ? wsum[wid - 1] : 0);
    int total = wsum[31];

    int run = excl;
    for (int i = 0; i < C; ++i) {
        int n = base + i;
        if (n < N) {
            int c = s[n];
            s[n] = run;
            run += c;
        }
    }
    __syncthreads();

    for (int i = t; i < N; i += 1024) {
        int o = s[i];
        g_offsets[i] = o;
        g_cursor[i]  = o;
    }
    if (t == 0) g_offsets[N] = total;
}

// ---------------------------------------------------------------------------
// Scatter src + ef rows into dst-sorted order. 16 edges/thread for MLP.
// ---------------------------------------------------------------------------
__global__ __launch_bounds__(256)
void build_kernel(const int* __restrict__ dst,
                  const int* __restrict__ src,
                  const float* __restrict__ ef, int E) {
    int t = blockIdx.x * 256 + threadIdx.x;
    int e16 = t * 16;
    if (e16 + 15 < E) {
        int pos[16];
        int sv[16];
#pragma unroll
        for (int q = 0; q < 4; ++q) {
            int4 d = *(const int4*)(dst + e16 + q * 4);
            int4 s = *(const int4*)(src + e16 + q * 4);
            pos[q * 4 + 0] = atomicAdd(&g_cursor[d.x], 1);
            pos[q * 4 + 1] = atomicAdd(&g_cursor[d.y], 1);
            pos[q * 4 + 2] = atomicAdd(&g_cursor[d.z], 1);
            pos[q * 4 + 3] = atomicAdd(&g_cursor[d.w], 1);
            sv[q * 4 + 0] = s.x << 8; sv[q * 4 + 1] = s.y << 8;
            sv[q * 4 + 2] = s.z << 8; sv[q * 4 + 3] = s.w << 8;
        }
        const float4* p = (const float4*)(ef + (size_t)e16 * 8);
#pragma unroll
        for (int j = 0; j < 16; ++j) {
            g_srcs[pos[j]] = sv[j];
            float4 a = p[j * 2];
            float4 b = p[j * 2 + 1];
            float4* q = (float4*)(g_efs + (size_t)pos[j] * 8);
            q[0] = a;
            q[1] = b;
        }
    } else {
        for (int e = e16; e < E; ++e) {
            int pp = atomicAdd(&g_cursor[dst[e]], 1);
            g_srcs[pp] = src[e] << 8;
            const float4* p = (const float4*)(ef + (size_t)e * 8);
            float4 a = p[0], b = p[1];
            float4* q = (float4*)(g_efs + (size_t)pp * 8);
            q[0] = a; q[1] = b;
        }
    }
}

// ---------------------------------------------------------------------------
__device__ __forceinline__ void ffma2(unsigned long long& d,
                                      unsigned long long a,
                                      unsigned long long b) {
    asm("fma.rn.f32x2 %0, %1, %2, %0;" : "+l"(d) : "l"(a), "l"(b));
}
__device__ __forceinline__ unsigned long long dupf(float v) {
    unsigned long long r;
    asm("mov.b64 %0, {%1, %1};" : "=l"(r) : "r"(__float_as_uint(v)));
    return r;
}
__device__ __forceinline__ float2 unpack2(unsigned long long v) {
    unsigned int lo, hi;
    asm("mov.b64 {%0, %1}, %2;" : "=r"(lo), "=r"(hi) : "l"(v));
    return make_float2(__uint_as_float(lo), __uint_as_float(hi));
}

// ---------------------------------------------------------------------------
// TWO warps per node (column-split). gw = global warp; node = gw>>1,
// half = gw&1; lane owns column c = half*32 + lane.
// acc[kp] = (out[2kp][c], out[2kp+1][c]) packed f32x2, bias-initialized.
// Per 32-edge batch: lane-parallel resolve into smem. Inner loop over 4-edge
// groups, z loads (scalar, LDG.32) pipelined one group ahead.
// ---------------------------------------------------------------------------
__global__ __launch_bounds__(256)
void gather_kernel(const float* __restrict__ bias,
                   float* __restrict__ out, int N) {
    __shared__ __align__(16) float4 sA[8][32];
    __shared__ __align__(16) float4 sB[8][32];
    __shared__ __align__(16) int sOf[8][32];
    int wblk = threadIdx.x >> 5;
    int gw   = (blockIdx.x * blockDim.x + threadIdx.x) >> 5;
    int lane = threadIdx.x & 31;
    int node = gw >> 1;
    int half = gw & 1;
    if (node >= N) return;

    int start = g_offsets[node];
    int cnt   = g_offsets[node + 1] - start;

    float bcol = bias[half * 32 + lane];
    unsigned long long acc[4];
    unsigned long long binit = dupf(bcol);
#pragma unroll
    for (int kp = 0; kp < 4; ++kp) acc[kp] = binit;

    const char* zl = (const char*)g_z + half * 128 + lane * 4;

    for (int base = 0; base < cnt; base += 32) {
        int m = min(32, cnt - base);
        int idx = start + base + lane;
        int off = 0;
        float4 ea = make_float4(0.f, 0.f, 0.f, 0.f);
        float4 eb = make_float4(0.f, 0.f, 0.f, 0.f);
        if (lane < m) {
            off = g_srcs[idx];
            const float4* p = (const float4*)(g_efs + (size_t)idx * 8);
            ea = p[0];
            eb = p[1];
        }
        sOf[wblk][lane] = off;
        sA[wblk][lane] = ea;
        sB[wblk][lane] = eb;
        __syncwarp();

        int groups = (m + 3) >> 2;
        int last = groups - 1;

        int4 o4 = *(const int4*)&sOf[wblk][0];
        float z0 = *(const float*)(zl + o4.x);
        float z1 = *(const float*)(zl + o4.y);
        float z2 = *(const float*)(zl + o4.z);
        float z3 = *(const float*)(zl + o4.w);

        for (int g = 0; g < groups; ++g) {
            int gn = (g < last) ? g + 1 : last;
            int4 o4n = *(const int4*)&sOf[wblk][gn * 4];
            float y0 = *(const float*)(zl + o4n.x);
            float y1 = *(const float*)(zl + o4n.y);
            float y2 = *(const float*)(zl + o4n.z);
            float y3 = *(const float*)(zl + o4n.w);

#pragma unroll
            for (int j = 0; j < 4; ++j) {
                float zj = (j == 0) ? z0 : (j == 1) ? z1 : (j == 2) ? z2 : z3;
                int e = g * 4 + j;
                ulonglong2 eA = *(const ulonglong2*)&sA[wblk][e];
                ulonglong2 eB = *(const ulonglong2*)&sB[wblk][e];
                unsigned long long zd = dupf(zj);
                ffma2(acc[0], eA.x, zd);
                ffma2(acc[1], eA.y, zd);
                ffma2(acc[2], eB.x, zd);
                ffma2(acc[3], eB.y, zd);
            }
            z0 = y0; z1 = y1; z2 = y2; z3 = y3;
        }
        __syncwarp();
    }

    float* op = out + (size_t)node * 512 + half * 32 + lane;
#pragma unroll
    for (int kp = 0; kp < 4; ++kp) {
        float2 p = unpack2(acc[kp]);     // (out[2kp][c], out[2kp+1][c])
        op[(2 * kp) * 64]     = p.x;
        op[(2 * kp + 1) * 64] = p.y;
    }
}

// ---------------------------------------------------------------------------
extern "C" void kernel_launch(void* const* d_in, const int* in_sizes, int n_in,
                              void* d_out, int out_size) {
    const float* node_feat = (const float*)d_in[0];
    const float* edge_feat = (const float*)d_in[1];
    const float* W         = (const float*)d_in[2];
    const float* b         = (const float*)d_in[3];
    const int*   src       = (const int*)d_in[4];
    const int*   dst       = (const int*)d_in[5];
    float*       out       = (float*)d_out;

    int N = in_sizes[0] / 64;
    int E = in_sizes[4];

    size_t scan_smem = (size_t)(N + 32) * sizeof(int);
    cudaFuncSetAttribute(scan_kernel,
                         cudaFuncAttributeMaxDynamicSharedMemorySize,
                         (int)scan_smem);

    int zb = (N + 63) / 64;
    zhist_kernel<<<zb, 256>>>(node_feat, W, dst, N, E);
    scan_kernel<<<1, 1024, scan_smem>>>(N);
    build_kernel<<<((E + 15) / 16 + 255) / 256, 256>>>(dst, src, edge_feat, E);
    gather_kernel<<<(N * 64 + 255) / 256, 256>>>(b, out, N);
}

// round 10
// speedup vs baseline: 1.2654x; 1.2654x over previous
#include <cuda_runtime.h>

// EfConv: out[n, k*64+o] = b[o] + sum_{e: dst[e]==n} edge_feat[e,k] * z[src[e], o]
// where z = node_feat @ W^T.
//
// Pipeline:
//   0. zhist_kernel : z = nf @ W^T (64 nodes/block, 4x4 reg tile, packed
//                     f32x2 FFMA) + histogram
//   1. scan_kernel  : smem-resident scan (warp-shuffle hierarchy); re-zeros counts
//   2. build_kernel : scatter (src<<8) + ef rows into CSR order (8 edges/thr)
//   3. gather_kernel: warp-per-node (R8 structure), batch-resolve into smem,
//                     z loads pipelined across 4-edge groups; minBlocks=5 to
//                     lift occupancy (reg-capped at 4 blocks/SM before).

#define MAX_N 50000
#define MAX_E 800000

__device__ float g_z[MAX_N * 64];
__device__ int   g_counts[MAX_N];
__device__ int   g_offsets[MAX_N + 1];
__device__ int   g_cursor[MAX_N];
__device__ int   g_srcs[MAX_E];          // src<<8 (byte offset of z row)
__device__ float g_efs[(size_t)MAX_E * 8];

// ---------------------------------------------------------------------------
__device__ __forceinline__ void ffma2(unsigned long long& d,
                                      unsigned long long a,
                                      unsigned long long b) {
    asm("fma.rn.f32x2 %0, %1, %2, %0;" : "+l"(d) : "l"(a), "l"(b));
}
__device__ __forceinline__ unsigned long long dupf(float v) {
    unsigned long long r;
    asm("mov.b64 %0, {%1, %1};" : "=l"(r) : "r"(__float_as_uint(v)));
    return r;
}
__device__ __forceinline__ float2 unpack2(unsigned long long v) {
    unsigned int lo, hi;
    asm("mov.b64 {%0, %1}, %2;" : "=r"(lo), "=r"(hi) : "l"(v));
    return make_float2(__uint_as_float(lo), __uint_as_float(hi));
}

// ---------------------------------------------------------------------------
// z = nf @ W^T, 64 nodes/block, thread = 4 nodes x 2 out-pairs (f32x2).
// Plus grid-stride int4 histogram of dst.
// ---------------------------------------------------------------------------
__global__ __launch_bounds__(256)
void zhist_kernel(const float* __restrict__ nf,
                  const float* __restrict__ W,
                  const int* __restrict__ dst, int N, int E) {
    __shared__ float Ws[64 * 68];    // Ws[i*68+o] = W[o*64+i] (68 = 4*17, float4-aligned)
    __shared__ float nfs[64 * 64];
    int tid = threadIdx.x;

#pragma unroll
    for (int it = 0; it < 16; ++it) {
        int idx = it * 256 + tid;            // idx = o*64 + i
        int o = idx >> 6, i = idx & 63;
        Ws[i * 68 + o] = W[idx];
    }

    int nb = blockIdx.x * 64;
#pragma unroll
    for (int it = 0; it < 16; ++it) {
        int idx = it * 256 + tid;
        int n = nb + (idx >> 6);
        nfs[idx] = (n < N) ? nf[(size_t)n * 64 + (idx & 63)] : 0.0f;
    }

    int gs = gridDim.x * 256;
    int quads = (E + 3) >> 2;
    for (int u = blockIdx.x * 256 + tid; u < quads; u += gs) {
        int e4 = u * 4;
        if (e4 + 3 < E) {
            int4 d = *(const int4*)(dst + e4);
            atomicAdd(&g_counts[d.x], 1);
            atomicAdd(&g_counts[d.y], 1);
            atomicAdd(&g_counts[d.z], 1);
            atomicAdd(&g_counts[d.w], 1);
        } else {
            for (int e = e4; e < E; ++e) atomicAdd(&g_counts[dst[e]], 1);
        }
    }
    __syncthreads();

    int ng = tid >> 4;        // node group 0..15
    int ow = tid & 15;        // out quad 0..15
    // accp[j][p] = packed pair (z[nj][ow*4+2p], z[nj][ow*4+2p+1])
    unsigned long long accp[4][2];
#pragma unroll
    for (int j = 0; j < 4; ++j) { accp[j][0] = 0ull; accp[j][1] = 0ull; }

#pragma unroll 4
    for (int i = 0; i < 64; ++i) {
        ulonglong2 wp = *(const ulonglong2*)(Ws + i * 68 + ow * 4);
        unsigned long long a0 = dupf(nfs[(ng * 4 + 0) * 64 + i]);
        unsigned long long a1 = dupf(nfs[(ng * 4 + 1) * 64 + i]);
        unsigned long long a2 = dupf(nfs[(ng * 4 + 2) * 64 + i]);
        unsigned long long a3 = dupf(nfs[(ng * 4 + 3) * 64 + i]);
        ffma2(accp[0][0], wp.x, a0);  ffma2(accp[0][1], wp.y, a0);
        ffma2(accp[1][0], wp.x, a1);  ffma2(accp[1][1], wp.y, a1);
        ffma2(accp[2][0], wp.x, a2);  ffma2(accp[2][1], wp.y, a2);
        ffma2(accp[3][0], wp.x, a3);  ffma2(accp[3][1], wp.y, a3);
    }

#pragma unroll
    for (int j = 0; j < 4; ++j) {
        int n = nb + ng * 4 + j;
        if (n < N)
            *(ulonglong2*)(g_z + (size_t)n * 64 + ow * 4) =
                make_ulonglong2(accp[j][0], accp[j][1]);
    }
}

// ---------------------------------------------------------------------------
__global__ __launch_bounds__(1024)
void scan_kernel(int N) {
    extern __shared__ int ss[];
    int* s     = ss;          // [N]
    int* wsum  = ss + N;      // [32]
    int t    = threadIdx.x;
    int lane = t & 31;
    int wid  = t >> 5;
    int C = (N + 1023) >> 10;

    for (int i = t; i < N; i += 1024) {
        s[i] = g_counts[i];
        g_counts[i] = 0;
    }
    __syncthreads();

    int base = t * C;
    int sum = 0;
    for (int i = 0; i < C; ++i) {
        int n = base + i;
        if (n < N) sum += s[n];
    }

    int v = sum;
#pragma unroll
    for (int d = 1; d < 32; d <<= 1) {
        int u = __shfl_up_sync(0xffffffffu, v, d);
        if (lane >= d) v += u;
    }
    if (lane == 31) wsum[wid] = v;
    __syncthreads();

    if (wid == 0) {
        int wv = wsum[lane];
#pragma unroll
        for (int d = 1; d < 32; d <<= 1) {
            int u = __shfl_up_sync(0xffffffffu, wv, d);
            if (lane >= d) wv += u;
        }
        wsum[lane] = wv;
    }
    __syncthreads();

    int excl = v - sum + (wid > 0 ? wsum[wid - 1] : 0);
    int total = wsum[31];

    int run = excl;
    for (int i = 0; i < C; ++i) {
        int n = base + i;
        if (n < N) {
            int c = s[n];
            s[n] = run;
            run += c;
        }
    }
    __syncthreads();

    for (int i = t; i < N; i += 1024) {
        int o = s[i];
        g_offsets[i] = o;
        g_cursor[i]  = o;
    }
    if (t == 0) g_offsets[N] = total;
}

// ---------------------------------------------------------------------------
// Scatter src + ef rows into dst-sorted order. 8 edges/thread for MLP on the
// ~318-cyc ATOMG chain.
// ---------------------------------------------------------------------------
__global__ __launch_bounds__(256)
void build_kernel(const int* __restrict__ dst,
                  const int* __restrict__ src,
                  const float* __restrict__ ef, int E) {
    int t = blockIdx.x * 256 + threadIdx.x;
    int e8 = t * 8;
    if (e8 + 7 < E) {
        int4 d0 = *(const int4*)(dst + e8);
        int4 d1 = *(const int4*)(dst + e8 + 4);
        int4 s0 = *(const int4*)(src + e8);
        int4 s1 = *(const int4*)(src + e8 + 4);
        int p0 = atomicAdd(&g_cursor[d0.x], 1);
        int p1 = atomicAdd(&g_cursor[d0.y], 1);
        int p2 = atomicAdd(&g_cursor[d0.z], 1);
        int p3 = atomicAdd(&g_cursor[d0.w], 1);
        int p4 = atomicAdd(&g_cursor[d1.x], 1);
        int p5 = atomicAdd(&g_cursor[d1.y], 1);
        int p6 = atomicAdd(&g_cursor[d1.z], 1);
        int p7 = atomicAdd(&g_cursor[d1.w], 1);
        const float4* p = (const float4*)(ef + (size_t)e8 * 8);
        g_srcs[p0] = s0.x << 8; g_srcs[p1] = s0.y << 8;
        g_srcs[p2] = s0.z << 8; g_srcs[p3] = s0.w << 8;
        g_srcs[p4] = s1.x << 8; g_srcs[p5] = s1.y << 8;
        g_srcs[p6] = s1.z << 8; g_srcs[p7] = s1.w << 8;
        int pos[8] = {p0, p1, p2, p3, p4, p5, p6, p7};
#pragma unroll
        for (int j = 0; j < 8; ++j) {
            float4 a = p[j * 2];
            float4 b = p[j * 2 + 1];
            float4* q = (float4*)(g_efs + (size_t)pos[j] * 8);
            q[0] = a;
            q[1] = b;
        }
    } else {
        for (int e = e8; e < E; ++e) {
            int pp = atomicAdd(&g_cursor[dst[e]], 1);
            g_srcs[pp] = src[e] << 8;
            const float4* p = (const float4*)(ef + (size_t)e * 8);
            float4 a = p[0], b = p[1];
            float4* q = (float4*)(g_efs + (size_t)pp * 8);
            q[0] = a; q[1] = b;
        }
    }
}

// ---------------------------------------------------------------------------
// Warp per node (R8 structure), minBlocksPerMultiprocessor=5 to force regs
// <= 51 and lift occupancy from 4 to 5 blocks/SM.
// acc[kp] = (out[2kp][c0], out[2kp+1][c0]) packed f32x2, acc[4+kp] for c1,
// (c0,c1) = (2*lane, 2*lane+1). Per 32-edge batch: lane-parallel resolve into
// conflict-free smem; inner loop over 4-edge groups with z loads pipelined
// one group ahead (clamped index, branch-free).
// ---------------------------------------------------------------------------
__global__ __launch_bounds__(256, 5)
void gather_kernel(const float* __restrict__ bias,
                   float* __restrict__ out, int N) {
    __shared__ __align__(16) float4 sA[8][32];
    __shared__ __align__(16) float4 sB[8][32];
    __shared__ __align__(16) int sOf[8][32];
    int wblk = threadIdx.x >> 5;
    int w    = (blockIdx.x * blockDim.x + threadIdx.x) >> 5;
    int lane = threadIdx.x & 31;
    if (w >= N) return;

    int start = g_offsets[w];
    int cnt   = g_offsets[w + 1] - start;

    float2 bv = ((const float2*)bias)[lane];
    unsigned long long acc[8];
#pragma unroll
    for (int kp = 0; kp < 4; ++kp) {
        acc[kp]     = dupf(bv.x);
        acc[4 + kp] = dupf(bv.y);
    }

    const char* zl = (const char*)g_z + lane * 8;

    for (int base = 0; base < cnt; base += 32) {
        int m = min(32, cnt - base);
        int idx = start + base + lane;
        int off = 0;
        float4 ea = make_float4(0.f, 0.f, 0.f, 0.f);
        float4 eb = make_float4(0.f, 0.f, 0.f, 0.f);
        if (lane < m) {
            off = g_srcs[idx];
            const float4* p = (const float4*)(g_efs + (size_t)idx * 8);
            ea = p[0];
            eb = p[1];
        }
        sOf[wblk][lane] = off;
        sA[wblk][lane] = ea;
        sB[wblk][lane] = eb;
        __syncwarp();

        int groups = (m + 3) >> 2;
        int last = groups - 1;

        int4 o4 = *(const int4*)&sOf[wblk][0];
        float2 z0 = *(const float2*)(zl + o4.x);
        float2 z1 = *(const float2*)(zl + o4.y);
        float2 z2 = *(const float2*)(zl + o4.z);
        float2 z3 = *(const float2*)(zl + o4.w);

        for (int g = 0; g < groups; ++g) {
            int gn = (g < last) ? g + 1 : last;
            int4 o4n = *(const int4*)&sOf[wblk][gn * 4];
            float2 y0 = *(const float2*)(zl + o4n.x);
            float2 y1 = *(const float2*)(zl + o4n.y);
            float2 y2 = *(const float2*)(zl + o4n.z);
            float2 y3 = *(const float2*)(zl + o4n.w);

#pragma unroll
            for (int j = 0; j < 4; ++j) {
                float2 zj = (j == 0) ? z0 : (j == 1) ? z1 : (j == 2) ? z2 : z3;
                int e = g * 4 + j;
                ulonglong2 eA = *(const ulonglong2*)&sA[wblk][e];
                ulonglong2 eB = *(const ulonglong2*)&sB[wblk][e];
                unsigned long long zx = dupf(zj.x);
                unsigned long long zy = dupf(zj.y);
                ffma2(acc[0], eA.x, zx);  ffma2(acc[4], eA.x, zy);
                ffma2(acc[1], eA.y, zx);  ffma2(acc[5], eA.y, zy);
                ffma2(acc[2], eB.x, zx);  ffma2(acc[6], eB.x, zy);
                ffma2(acc[3], eB.y, zx);  ffma2(acc[7], eB.y, zy);
            }
            z0 = y0; z1 = y1; z2 = y2; z3 = y3;
        }
        __syncwarp();
    }

    float* op = out + (size_t)w * 512 + 2 * lane;
#pragma unroll
    for (int kp = 0; kp < 4; ++kp) {
        float2 lo = unpack2(acc[kp]);
        float2 hi = unpack2(acc[4 + kp]);
        *(float2*)(op + (2 * kp) * 64)     = make_float2(lo.x, hi.x);
        *(float2*)(op + (2 * kp + 1) * 64) = make_float2(lo.y, hi.y);
    }
}

// ---------------------------------------------------------------------------
extern "C" void kernel_launch(void* const* d_in, const int* in_sizes, int n_in,
                              void* d_out, int out_size) {
    const float* node_feat = (const float*)d_in[0];
    const float* edge_feat = (const float*)d_in[1];
    const float* W         = (const float*)d_in[2];
    const float* b         = (const float*)d_in[3];
    const int*   src       = (const int*)d_in[4];
    const int*   dst       = (const int*)d_in[5];
    float*       out       = (float*)d_out;

    int N = in_sizes[0] / 64;
    int E = in_sizes[4];

    size_t scan_smem = (size_t)(N + 32) * sizeof(int);
    cudaFuncSetAttribute(scan_kernel,
                         cudaFuncAttributeMaxDynamicSharedMemorySize,
                         (int)scan_smem);

    int zb = (N + 63) / 64;
    zhist_kernel<<<zb, 256>>>(node_feat, W, dst, N, E);
    scan_kernel<<<1, 1024, scan_smem>>>(N);
    build_kernel<<<((E + 7) / 8 + 255) / 256, 256>>>(dst, src, edge_feat, E);
    gather_kernel<<<(N * 32 + 255) / 256, 256>>>(b, out, N);
}